// round 12
// baseline (speedup 1.0000x reference)
#include <cuda_runtime.h>
#include <cuda_fp16.h>
#include <cstdint>
#include <math.h>

// Problem constants
#define NB 64
#define NN 256
#define NS 2000
#define KK 100
#define BIL 4
#define NITERS 200

#define L_PAD 129                       // half2 per padded row (128 + 1)
#define L_SMEM_BYTES (NN * L_PAD * 4)   // 132096 B
#define DYN_FLOATS 8000
#define DYN_BYTES (L_SMEM_BYTES + DYN_FLOATS * 4)   // 164096 B

// Device scratch
__device__ __align__(16) __half g_L16[(size_t)NB * NN * NN];   // 8.4MB  L[b][m][n]
__device__ __align__(16) __half g_eps16[(size_t)NB * NS * NN]; // 65.5MB row-major [b][s][n]
__device__ __align__(16) __half g_epsT[(size_t)NB * NN * NS];  // 65.5MB transposed [b][n][s]

// ---------------------------------------------------------------------------
__device__ __forceinline__ unsigned int smem_u32(const void* p) {
    unsigned int a;
    asm("{ .reg .u64 t; cvta.to.shared.u64 t, %1; cvt.u32.u64 %0, t; }"
        : "=r"(a) : "l"(p));
    return a;
}
__device__ __forceinline__ float ld_peer_f32(unsigned int addr, unsigned int prank) {
    unsigned int pa;
    asm("mapa.shared::cluster.u32 %0, %1, %2;" : "=r"(pa) : "r"(addr), "r"(prank));
    float v;
    asm volatile("ld.shared::cluster.f32 %0, [%1];" : "=f"(v) : "r"(pa));
    return v;
}
__device__ __forceinline__ void cluster_sync_() {
    asm volatile("barrier.cluster.arrive.aligned;" ::: "memory");
    asm volatile("barrier.cluster.wait.aligned;" ::: "memory");
}

// ---------------------------------------------------------------------------
// eps fp32 -> fp16 row-major (one thread per 8 elements)
// ---------------------------------------------------------------------------
extern "C" __global__ void __launch_bounds__(256)
conv_kernel(const float* __restrict__ eps)
{
    size_t gid = (size_t)blockIdx.x * blockDim.x + threadIdx.x;
    const size_t total8 = (size_t)NB * NS * NN / 8;
    if (gid >= total8) return;
    const float4* e4 = (const float4*)eps;
    float4 f0 = __ldcs(e4 + 2 * gid);
    float4 f1 = __ldcs(e4 + 2 * gid + 1);
    uint4 o;
    *(__half2*)&o.x = __floats2half2_rn(f0.x, f0.y);
    *(__half2*)&o.y = __floats2half2_rn(f0.z, f0.w);
    *(__half2*)&o.z = __floats2half2_rn(f1.x, f1.y);
    *(__half2*)&o.w = __floats2half2_rn(f1.z, f1.w);
    ((uint4*)g_eps16)[gid] = o;
}

// ---------------------------------------------------------------------------
// eps fp32 -> fp16 transposed [b][n][s], tiled 64(s) x 32(n)
// ---------------------------------------------------------------------------
extern "C" __global__ void __launch_bounds__(256)
transpose_kernel(const float* __restrict__ eps)
{
    __shared__ float tile[64][33];
    const int blk = blockIdx.x;
    const int b = blk >> 8;
    const int rest = blk & 255;
    const int st = rest >> 3;
    const int nt = rest & 7;
    const int s0 = st * 64, n0 = nt * 32;
    const int tid = threadIdx.x;

    #pragma unroll
    for (int k = 0; k < 8; ++k) {
        int idx = tid + 256 * k;
        int s = idx >> 5, n = idx & 31;
        float v = 0.0f;
        if (s0 + s < NS) v = __ldcs(&eps[((size_t)b * NS + s0 + s) * NN + n0 + n]);
        tile[s][n] = v;
    }
    __syncthreads();
    #pragma unroll
    for (int k = 0; k < 4; ++k) {
        int idx = tid + 256 * k;
        int n = idx >> 5, sp = idx & 31;
        int s = 2 * sp;
        if (s0 + s < NS) {
            __half2 h = __floats2half2_rn(tile[s][n], tile[s + 1][n]);
            *(__half2*)(g_epsT + ((size_t)b * NN + n0 + n) * NS + s0 + s) = h;
        }
    }
}

// ---------------------------------------------------------------------------
// Cholesky: one block per batch, packed lower triangle in smem; fp16 L out.
// ---------------------------------------------------------------------------
__device__ __forceinline__ int tri_row_of(int idx) {
    float f = sqrtf(8.0f * (float)idx + 1.0f);
    int i = (int)((f - 1.0f) * 0.5f);
    while ((i + 1) * (i + 2) / 2 <= idx) ++i;
    while (i * (i + 1) / 2 > idx) --i;
    return i;
}

extern "C" __global__ void __launch_bounds__(256)
chol_kernel(const float* __restrict__ sigma) {
    extern __shared__ float sm[];   // 32896 floats
    const int b = blockIdx.x;
    const int tid = threadIdx.x;
    const float* A = sigma + (size_t)b * NN * NN;

    for (int idx = tid; idx < 32896; idx += 256) {
        int i = tri_row_of(idx);
        int j = idx - i * (i + 1) / 2;
        float v = A[i * NN + j];
        if (i == j) v += 1e-4f;
        sm[idx] = v;
    }
    __syncthreads();

    __shared__ float sdiag;
    float acc = 0.0f;
    const int base_i = tid * (tid + 1) / 2;

    for (int j = 0; j < NN; ++j) {
        if (tid == j) {
            float d = sm[j * (j + 1) / 2 + j] - acc;
            sdiag = sqrtf(fmaxf(d, 1e-20f));
            sm[j * (j + 1) / 2 + j] = sdiag;
        }
        __syncthreads();
        float dinv = 1.0f / sdiag;
        if (tid > j) {
            const int base_j = j * (j + 1) / 2;
            float s = sm[base_i + j];
            int k = 0;
            for (; k + 4 <= j; k += 4) {
                s -= sm[base_i + k]     * sm[base_j + k];
                s -= sm[base_i + k + 1] * sm[base_j + k + 1];
                s -= sm[base_i + k + 2] * sm[base_j + k + 2];
                s -= sm[base_i + k + 3] * sm[base_j + k + 3];
            }
            for (; k < j; ++k) s -= sm[base_i + k] * sm[base_j + k];
            float lij = s * dinv;
            sm[base_i + j] = lij;
            acc += lij * lij;
        }
        __syncthreads();
    }

    __half* Lb = g_L16 + (size_t)b * NN * NN;
    for (int idx = tid; idx < NN * NN; idx += 256) {
        int i = idx >> 8, j = idx & 255;
        Lb[idx] = __float2half_rn((j <= i) ? sm[i * (i + 1) / 2 + j] : 0.0f);
    }
}

// ---------------------------------------------------------------------------
// Fast simplex projection (values on tid<256).
// ---------------------------------------------------------------------------
__device__ __forceinline__ float simplex_proj_fast(
    float wv, float z, int tid, int lane,
    float* ssort, float* scs, float* swsumf)
{
    float x = wv;

#define SP_SHFL(kk, jj) \
    if (tid < 256) { \
        float o = __shfl_xor_sync(0xffffffffu, x, (jj)); \
        bool keepMax = (((tid & (kk)) == 0) == ((tid & (jj)) == 0)); \
        x = keepMax ? fmaxf(x, o) : fminf(x, o); \
    }
#define SP_SMEM(kk, jj) { \
    if (tid < 256) ssort[tid] = x; \
    __syncthreads(); \
    if (tid < 256) { \
        float o = ssort[tid ^ (jj)]; \
        bool keepMax = (((tid & (kk)) == 0) == ((tid & (jj)) == 0)); \
        x = keepMax ? fmaxf(x, o) : fminf(x, o); \
    } \
    __syncthreads(); }

    SP_SHFL(2, 1)
    SP_SHFL(4, 2)  SP_SHFL(4, 1)
    SP_SHFL(8, 4)  SP_SHFL(8, 2)  SP_SHFL(8, 1)
    SP_SHFL(16, 8) SP_SHFL(16, 4) SP_SHFL(16, 2) SP_SHFL(16, 1)
    SP_SHFL(32, 16) SP_SHFL(32, 8) SP_SHFL(32, 4) SP_SHFL(32, 2) SP_SHFL(32, 1)
    SP_SMEM(64, 32)
    SP_SHFL(64, 16) SP_SHFL(64, 8) SP_SHFL(64, 4) SP_SHFL(64, 2) SP_SHFL(64, 1)
    SP_SMEM(128, 64) SP_SMEM(128, 32)
    SP_SHFL(128, 16) SP_SHFL(128, 8) SP_SHFL(128, 4) SP_SHFL(128, 2) SP_SHFL(128, 1)
    SP_SMEM(256, 128) SP_SMEM(256, 64) SP_SMEM(256, 32)
    SP_SHFL(256, 16) SP_SHFL(256, 8) SP_SHFL(256, 4) SP_SHFL(256, 2) SP_SHFL(256, 1)
#undef SP_SHFL
#undef SP_SMEM

    float inc = 0.0f;
    if (tid < 256) {
        inc = x;
        #pragma unroll
        for (int off = 1; off < 32; off <<= 1) {
            float v = __shfl_up_sync(0xffffffffu, inc, off);
            if (lane >= off) inc += v;
        }
        if (lane == 31) swsumf[tid >> 5] = inc;
    }
    __syncthreads();
    bool cond = false;
    if (tid < 256) {
        float pre = 0.0f;
        int w = tid >> 5;
        #pragma unroll
        for (int q = 0; q < 8; ++q) if (q < w) pre += swsumf[q];
        float cs = inc + pre;
        scs[tid] = cs;
        cond = (x - (cs - z) / (float)(tid + 1)) > 0.0f;
    }
    int rho = __syncthreads_count(cond ? 1 : 0);
    float theta = (scs[rho - 1] - z) / (float)rho;
    return fmaxf(wv - theta, 0.0f);
}

// ---------------------------------------------------------------------------
// u = L^T w from SMEM L (padded, conflict-free columns).
// ---------------------------------------------------------------------------
__device__ __forceinline__ void compute_u_smem(
    int tid, const __half2* sL2, const float* sw, float* sbuf, float* su)
{
    const int q = tid >> 7, cp = tid & 127;
    const __half2* base = sL2 + (size_t)(32 * q) * L_PAD + cp;
    float2 acc = make_float2(0.0f, 0.0f);
    #pragma unroll 8
    for (int m = 0; m < 32; ++m) {
        float2 f = __half22float2(base[m * L_PAD]);
        float wm = sw[32 * q + m];
        acc.x += f.x * wm; acc.y += f.y * wm;
    }
    ((float2*)sbuf)[q * 128 + cp] = acc;
    __syncthreads();
    if (tid < 128) {
        float2 s = make_float2(0.0f, 0.0f);
        #pragma unroll
        for (int r = 0; r < 8; ++r) {
            float2 v = ((const float2*)sbuf)[r * 128 + tid];
            s.x += v.x; s.y += v.y;
        }
        su[2 * tid] = s.x;
        su[2 * tid + 1] = s.y;
    }
}

// ---------------------------------------------------------------------------
// Radix-digest: warp0 scans the 256-bin histogram (descending digits) and
// updates (s_P, s_k) for the K-th largest key.
// ---------------------------------------------------------------------------
__device__ __forceinline__ void radix_digest(
    int lane, int shift, const int* shist, unsigned* s_P, int* s_k)
{
    const unsigned Pc = *s_P;
    const int kcur = *s_k;
    int c[8]; int sum = 0;
    #pragma unroll
    for (int j = 0; j < 8; ++j) { c[j] = shist[255 - (lane * 8 + j)]; sum += c[j]; }
    int incs = sum;
    #pragma unroll
    for (int off = 1; off < 32; off <<= 1) {
        int v = __shfl_up_sync(0xffffffffu, incs, off);
        if (lane >= off) incs += v;
    }
    int run = incs - sum;
    #pragma unroll
    for (int j = 0; j < 8; ++j) {
        int C1 = run; run += c[j];
        if (run >= kcur && C1 < kcur) {
            *s_P = Pc | ((unsigned)(255 - (lane * 8 + j)) << shift);
            *s_k = kcur - C1;
        }
    }
}

// ---------------------------------------------------------------------------
// Persistent solver: cluster of 2 CTAs per batch. Rank r streams the
// n in [128r, 128r+128) half of epsT (default cache policy -> epsT stays
// L2-resident: 65.5MB < 126MB L2); partial losses exchanged via DSMEM.
// ---------------------------------------------------------------------------
extern "C" __global__ void __launch_bounds__(1024, 1) __cluster_dims__(2, 1, 1)
persist_kernel(const float* __restrict__ mu,
               const int* __restrict__ p_crisis, const int* __restrict__ p_lambda,
               float* __restrict__ out)
{
    extern __shared__ char dynraw[];
    __half2* sL2 = (__half2*)dynraw;                    // [256][129] padded L
    float* dynf  = (float*)(dynraw + L_SMEM_BYTES);     // 8000 floats
    float* spart = dynf;                                // [4][2000] loss partials
    unsigned* scand = (unsigned*)dynf;                  // [<=2000] candidate keys (alias)
    int*   ssel  = (int*)dynf;                          // [2000] selected idx (alias)
    float* sbuf  = dynf + 2048;                         // [2048]
    float2* svv2 = (float2*)(dynf + 4352);              // [128]  v pairs

    __shared__ float su[256], sw[256], ssort[256], scs[256];
    __shared__ unsigned skey[NS];
    __shared__ int shist[256];
    __shared__ float swsumf[8];
    __shared__ int swsum[32];
    __shared__ unsigned s_P;
    __shared__ int s_k, s_ncand;

    const int b = blockIdx.x >> 1;
    const unsigned int rank = blockIdx.x & 1;
    const unsigned int prank = rank ^ 1;
    const int tid = threadIdx.x;
    const int lane = tid & 31;
    const int warp = tid >> 5;

    const float crisis = (float)(*p_crisis);
    const int lam = *p_lambda;
    const float lamscale = (lam > 0) ? (1.0f + 1.0f / fmaxf((float)lam, 0.1f)) : 1.0f;
    const float z = 1.0f - 0.5f * crisis;
    const float flme = (tid == BIL) ? 0.5f * crisis : 0.0f;
    float mue = 0.0f;
    if (tid < 256) mue = mu[b * NN + tid] * lamscale;

    // load L into padded smem (bank-conflict-free in both orientations)
    {
        const __half2* Lg2 = (const __half2*)(g_L16 + (size_t)b * NN * NN);
        for (int idx = tid; idx < NN * 128; idx += 1024) {
            int row = idx >> 7, col = idx & 127;
            sL2[row * L_PAD + col] = Lg2[idx];
        }
    }

    // loss-phase mapping: 1000 active threads; nc in [0,4) owns 32 n's within
    // this rank's 128-n half, sg in [0,250) owns 8 scenarios.
    const int nc = tid / 250;
    const int sg = tid - nc * 250;
    const bool lactive = (tid < 1000);
    const unsigned int spart_a = smem_u32(spart);

    // ---- init: w0 = proj(uniform), u = L^T w0
    {
        float v = (1.0f / (float)NN) - flme;
        float pw = simplex_proj_fast(v, z, tid, lane, ssort, scs, swsumf) + flme;
        if (tid < 256) sw[tid] = pw;
        __syncthreads();
        compute_u_smem(tid, sL2, sw, sbuf, su);
        __syncthreads();
    }
    cluster_sync_();   // both ranks ready before first loss exchange cycle

    for (int t = 0; t < NITERS; ++t) {
        // ---- loss phase: partial dots over this rank's 128 n's
        // default-policy loads keep epsT L2-resident across iterations
        if (lactive) {
            const int nbase = (int)rank * 128 + nc * 32;
            const __half* base = g_epsT + ((size_t)(b * NN + nbase)) * NS + 8 * sg;
            float a0=0.f,a1=0.f,a2=0.f,a3=0.f,a4=0.f,a5=0.f,a6=0.f,a7=0.f;
            #pragma unroll 8
            for (int n = 0; n < 32; ++n) {
                uint4 raw = __ldg((const uint4*)(base + (size_t)n * NS));
                float un = su[nbase + n];
                float2 f0 = __half22float2(*(const __half2*)&raw.x);
                float2 f1 = __half22float2(*(const __half2*)&raw.y);
                float2 f2 = __half22float2(*(const __half2*)&raw.z);
                float2 f3 = __half22float2(*(const __half2*)&raw.w);
                a0 += f0.x * un; a1 += f0.y * un;
                a2 += f1.x * un; a3 += f1.y * un;
                a4 += f2.x * un; a5 += f2.y * un;
                a6 += f3.x * un; a7 += f3.y * un;
            }
            float* o = spart + nc * NS + 8 * sg;
            o[0]=a0; o[1]=a1; o[2]=a2; o[3]=a3; o[4]=a4; o[5]=a5; o[6]=a6; o[7]=a7;
        }
        // zero pass-0 histogram + select state while loss stores drain
        if (tid < 256) shist[tid] = 0;
        if (tid == 0) { s_P = 0u; s_k = KK; s_ncand = 0; }
        __syncthreads();

        // combine my 4 sub-partials in place: spart[s] = my half-dot
        for (int s = tid; s < NS; s += 1024)
            spart[s] = (spart[s] + spart[NS + s]) + (spart[2 * NS + s] + spart[3 * NS + s]);
        __syncthreads();
        cluster_sync_();   // my half-dots visible to peer

        // full losses via DSMEM read of peer's half -> sortable keys
        // + FUSED radix pass-0 histogram
        for (int s = tid; s < NS; s += 1024) {
            float pv = ld_peer_f32(spart_a + 4 * (unsigned int)s, prank);
            float loss = -(spart[s] + pv);
            unsigned ub = __float_as_uint(loss);
            unsigned key = (ub & 0x80000000u) ? ~ub : (ub | 0x80000000u);
            skey[s] = key;
            atomicAdd(&shist[key >> 24], 1);
        }
        __syncthreads();
        if (warp == 0) radix_digest(lane, 24, shist, &s_P, &s_k);
        __syncthreads();
        cluster_sync_();   // peer done reading my spart; aliases may go live

        // ---- collect candidate keys sharing the pass-0 digit (order-free:
        // candidates are only counted in later passes, so atomic order is fine)
        const unsigned d0 = s_P >> 24;
        for (int s = tid; s < NS; s += 1024) {
            unsigned key = skey[s];
            if ((key >> 24) == d0) {
                int ix = atomicAdd(&s_ncand, 1);
                scand[ix] = key;
            }
        }
        __syncthreads();
        const int ncand = s_ncand;

        // ---- radix passes 1..3 over the (small) candidate set
        #pragma unroll
        for (int p = 1; p < 4; ++p) {
            const int shift = 24 - 8 * p;
            if (tid < 256) shist[tid] = 0;
            __syncthreads();
            const unsigned Pc = s_P;
            for (int i = tid; i < ncand; i += 1024) {
                unsigned key = scand[i];
                bool match = (p == 1) || ((key >> (shift + 8)) == (Pc >> (shift + 8)));
                if (match) atomicAdd(&shist[(key >> shift) & 255u], 1);
            }
            __syncthreads();
            if (warp == 0) radix_digest(lane, shift, shist, &s_P, &s_k);
            __syncthreads();
        }
        const unsigned T = s_P;

        // ---- deterministic compaction of selected scenarios
        bool m0 = skey[tid] >= T;
        bool m1 = (tid + 1024 < NS) && (skey[tid + 1024] >= T);
        int cnt = (int)m0 + (int)m1;
        {
            int incs = cnt;
            #pragma unroll
            for (int off = 1; off < 32; off <<= 1) {
                int v = __shfl_up_sync(0xffffffffu, incs, off);
                if (lane >= off) incs += v;
            }
            if (lane == 31) swsum[warp] = incs;
            __syncthreads();
            if (warp == 0) {
                int v = swsum[lane];
                #pragma unroll
                for (int off = 1; off < 32; off <<= 1) {
                    int x = __shfl_up_sync(0xffffffffu, v, off);
                    if (lane >= off) v += x;
                }
                swsum[lane] = v;
            }
            __syncthreads();
            int ofs = (incs - cnt) + (warp > 0 ? swsum[warp - 1] : 0);
            if (m0) ssel[ofs++] = tid;
            if (m1) ssel[ofs] = tid + 1024;
        }
        __syncthreads();
        const int total = swsum[31];
        const float coef = 1.0f / fmaxf((float)total, (float)KK);
        const float summ = (float)total * coef;

        // ---- v = coef * sum_{selected s} eps16[b,s,:]  (8-way row split,
        // 4-way unrolled for MLP; evict-first so the random gather never
        // pollutes epsT's L2 residency)
        {
            const int grp = tid >> 7, cp = tid & 127;
            const __half2* e2 = (const __half2*)g_eps16 + (size_t)b * NS * 128;
            float2 acc = make_float2(0.0f, 0.0f);
            int i = grp;
            for (; i + 24 < total; i += 32) {
                float2 fa = __half22float2(__ldcs(e2 + (size_t)ssel[i]      * 128 + cp));
                float2 fb = __half22float2(__ldcs(e2 + (size_t)ssel[i + 8]  * 128 + cp));
                float2 fc = __half22float2(__ldcs(e2 + (size_t)ssel[i + 16] * 128 + cp));
                float2 fd = __half22float2(__ldcs(e2 + (size_t)ssel[i + 24] * 128 + cp));
                acc.x += (fa.x + fb.x) + (fc.x + fd.x);
                acc.y += (fa.y + fb.y) + (fc.y + fd.y);
            }
            for (; i < total; i += 8) {
                float2 fa = __half22float2(__ldcs(e2 + (size_t)ssel[i] * 128 + cp));
                acc.x += fa.x; acc.y += fa.y;
            }
            ((float2*)sbuf)[grp * 128 + cp] = acc;
        }
        __syncthreads();
        if (tid < 128) {
            float2 s = make_float2(0.0f, 0.0f);
            #pragma unroll
            for (int r = 0; r < 8; ++r) {
                float2 v = ((const float2*)sbuf)[r * 128 + tid];
                s.x += v.x; s.y += v.y;
            }
            svv2[tid] = make_float2(s.x * coef, s.y * coef);
        }
        __syncthreads();

        // ---- lv[n] = sum_m L[n][m] v[m] from SMEM L (row access, conflict-free)
        {
            const int q = tid >> 8, n = tid & 255;
            const __half2* rowp = sL2 + (size_t)n * L_PAD + 32 * q;
            float acc = 0.0f;
            #pragma unroll 8
            for (int mp = 0; mp < 32; ++mp) {
                float2 f = __half22float2(rowp[mp]);
                float2 vv = svv2[32 * q + mp];
                acc += f.x * vv.x + f.y * vv.y;
            }
            sbuf[q * 256 + n] = acc;   // no alias with svv2; barrier not needed
        }
        __syncthreads();

        // ---- projected update (threads < 256 own components)
        const float lr = 0.5f / sqrtf((float)t + 1.0f);
        float wv = 0.0f;
        if (tid < 256) {
            float lv = sbuf[tid] + sbuf[256 + tid] + sbuf[512 + tid] + sbuf[768 + tid];
            const float gval = -(summ * mue + lv);
            wv = sw[tid] - lr * gval - flme;
        }
        __syncthreads();
        float pw = simplex_proj_fast(wv, z, tid, lane, ssort, scs, swsumf) + flme;
        if (tid < 256) sw[tid] = pw;
        __syncthreads();

        if (t == NITERS - 1) {
            // ---- final clamp + renormalize (rank 0 writes)
            float wc = (tid < 256) ? fmaxf(pw, 0.0f) : 0.0f;
            float r = wc;
            if (tid < 256) {
                #pragma unroll
                for (int off = 16; off > 0; off >>= 1)
                    r += __shfl_down_sync(0xffffffffu, r, off);
                if (lane == 0) swsumf[tid >> 5] = r;
            }
            __syncthreads();
            if (rank == 0 && tid < 256) {
                float s = 0.0f;
                #pragma unroll
                for (int q = 0; q < 8; ++q) s += swsumf[q];
                out[b * NN + tid] = wc / (s + 1e-8f);
            }
        } else {
            compute_u_smem(tid, sL2, sw, sbuf, su);
            __syncthreads();   // su stable & dyn free before next loss phase
        }
    }
    cluster_sync_();   // no rank exits while peer may still DSMEM-read
}

// ---------------------------------------------------------------------------
extern "C" void kernel_launch(void* const* d_in, const int* in_sizes, int n_in,
                              void* d_out, int out_size)
{
    const float* mu     = (const float*)d_in[0];
    const float* sigma  = (const float*)d_in[1];
    const float* eps    = (const float*)d_in[2];
    const int*   crisis = (const int*)d_in[3];
    const int*   lambda = (const int*)d_in[4];
    float* out = (float*)d_out;

    cudaFuncSetAttribute(chol_kernel, cudaFuncAttributeMaxDynamicSharedMemorySize,
                         32896 * sizeof(float));
    cudaFuncSetAttribute(persist_kernel, cudaFuncAttributeMaxDynamicSharedMemorySize,
                         DYN_BYTES);

    conv_kernel<<<16000, 256>>>(eps);
    transpose_kernel<<<NB * 256, 256>>>(eps);
    chol_kernel<<<NB, 256, 32896 * sizeof(float)>>>(sigma);
    persist_kernel<<<NB * 2, 1024, DYN_BYTES>>>(mu, crisis, lambda, out);
}

// round 13
// speedup vs baseline: 1.0516x; 1.0516x over previous
#include <cuda_runtime.h>
#include <cuda_fp16.h>
#include <cstdint>
#include <math.h>

// Problem constants
#define NB 64
#define NN 256
#define NS 2000
#define KK 100
#define BIL 4
#define NITERS 200

#define L_PAD 129                       // half2 per padded row (128 + 1)
#define L_SMEM_BYTES (NN * L_PAD * 4)   // 132096 B
#define DYN_FLOATS 8000
#define DYN_BYTES (L_SMEM_BYTES + DYN_FLOATS * 4)   // 164096 B

// Device scratch
__device__ __align__(16) __half g_L16[(size_t)NB * NN * NN];   // 8.4MB  L[b][m][n]
__device__ __align__(16) __half g_eps16[(size_t)NB * NS * NN]; // 65.5MB row-major [b][s][n]
__device__ __align__(16) __half g_epsT[(size_t)NB * NN * NS];  // 65.5MB transposed [b][n][s]

// ---------------------------------------------------------------------------
__device__ __forceinline__ unsigned int smem_u32(const void* p) {
    unsigned int a;
    asm("{ .reg .u64 t; cvta.to.shared.u64 t, %1; cvt.u32.u64 %0, t; }"
        : "=r"(a) : "l"(p));
    return a;
}
__device__ __forceinline__ float ld_peer_f32(unsigned int addr, unsigned int prank) {
    unsigned int pa;
    asm("mapa.shared::cluster.u32 %0, %1, %2;" : "=r"(pa) : "r"(addr), "r"(prank));
    float v;
    asm volatile("ld.shared::cluster.f32 %0, [%1];" : "=f"(v) : "r"(pa));
    return v;
}
__device__ __forceinline__ void cluster_sync_() {
    asm volatile("barrier.cluster.arrive.aligned;" ::: "memory");
    asm volatile("barrier.cluster.wait.aligned;" ::: "memory");
}

// ---------------------------------------------------------------------------
// eps fp32 -> fp16 row-major (one thread per 8 elements)
// ---------------------------------------------------------------------------
extern "C" __global__ void __launch_bounds__(256)
conv_kernel(const float* __restrict__ eps)
{
    size_t gid = (size_t)blockIdx.x * blockDim.x + threadIdx.x;
    const size_t total8 = (size_t)NB * NS * NN / 8;
    if (gid >= total8) return;
    const float4* e4 = (const float4*)eps;
    float4 f0 = __ldcs(e4 + 2 * gid);
    float4 f1 = __ldcs(e4 + 2 * gid + 1);
    uint4 o;
    *(__half2*)&o.x = __floats2half2_rn(f0.x, f0.y);
    *(__half2*)&o.y = __floats2half2_rn(f0.z, f0.w);
    *(__half2*)&o.z = __floats2half2_rn(f1.x, f1.y);
    *(__half2*)&o.w = __floats2half2_rn(f1.z, f1.w);
    ((uint4*)g_eps16)[gid] = o;
}

// ---------------------------------------------------------------------------
// eps fp32 -> fp16 transposed [b][n][s], tiled 64(s) x 32(n)
// ---------------------------------------------------------------------------
extern "C" __global__ void __launch_bounds__(256)
transpose_kernel(const float* __restrict__ eps)
{
    __shared__ float tile[64][33];
    const int blk = blockIdx.x;
    const int b = blk >> 8;
    const int rest = blk & 255;
    const int st = rest >> 3;
    const int nt = rest & 7;
    const int s0 = st * 64, n0 = nt * 32;
    const int tid = threadIdx.x;

    #pragma unroll
    for (int k = 0; k < 8; ++k) {
        int idx = tid + 256 * k;
        int s = idx >> 5, n = idx & 31;
        float v = 0.0f;
        if (s0 + s < NS) v = __ldcs(&eps[((size_t)b * NS + s0 + s) * NN + n0 + n]);
        tile[s][n] = v;
    }
    __syncthreads();
    #pragma unroll
    for (int k = 0; k < 4; ++k) {
        int idx = tid + 256 * k;
        int n = idx >> 5, sp = idx & 31;
        int s = 2 * sp;
        if (s0 + s < NS) {
            __half2 h = __floats2half2_rn(tile[s][n], tile[s + 1][n]);
            *(__half2*)(g_epsT + ((size_t)b * NN + n0 + n) * NS + s0 + s) = h;
        }
    }
}

// ---------------------------------------------------------------------------
// Cholesky: one block per batch, packed lower triangle in smem; fp16 L out.
// ---------------------------------------------------------------------------
__device__ __forceinline__ int tri_row_of(int idx) {
    float f = sqrtf(8.0f * (float)idx + 1.0f);
    int i = (int)((f - 1.0f) * 0.5f);
    while ((i + 1) * (i + 2) / 2 <= idx) ++i;
    while (i * (i + 1) / 2 > idx) --i;
    return i;
}

extern "C" __global__ void __launch_bounds__(256)
chol_kernel(const float* __restrict__ sigma) {
    extern __shared__ float sm[];   // 32896 floats
    const int b = blockIdx.x;
    const int tid = threadIdx.x;
    const float* A = sigma + (size_t)b * NN * NN;

    for (int idx = tid; idx < 32896; idx += 256) {
        int i = tri_row_of(idx);
        int j = idx - i * (i + 1) / 2;
        float v = A[i * NN + j];
        if (i == j) v += 1e-4f;
        sm[idx] = v;
    }
    __syncthreads();

    __shared__ float sdiag;
    float acc = 0.0f;
    const int base_i = tid * (tid + 1) / 2;

    for (int j = 0; j < NN; ++j) {
        if (tid == j) {
            float d = sm[j * (j + 1) / 2 + j] - acc;
            sdiag = sqrtf(fmaxf(d, 1e-20f));
            sm[j * (j + 1) / 2 + j] = sdiag;
        }
        __syncthreads();
        float dinv = 1.0f / sdiag;
        if (tid > j) {
            const int base_j = j * (j + 1) / 2;
            float s = sm[base_i + j];
            int k = 0;
            for (; k + 4 <= j; k += 4) {
                s -= sm[base_i + k]     * sm[base_j + k];
                s -= sm[base_i + k + 1] * sm[base_j + k + 1];
                s -= sm[base_i + k + 2] * sm[base_j + k + 2];
                s -= sm[base_i + k + 3] * sm[base_j + k + 3];
            }
            for (; k < j; ++k) s -= sm[base_i + k] * sm[base_j + k];
            float lij = s * dinv;
            sm[base_i + j] = lij;
            acc += lij * lij;
        }
        __syncthreads();
    }

    __half* Lb = g_L16 + (size_t)b * NN * NN;
    for (int idx = tid; idx < NN * NN; idx += 256) {
        int i = idx >> 8, j = idx & 255;
        Lb[idx] = __float2half_rn((j <= i) ? sm[i * (i + 1) / 2 + j] : 0.0f);
    }
}

// ---------------------------------------------------------------------------
// Fast simplex projection (values on tid<256).
// ---------------------------------------------------------------------------
__device__ __forceinline__ float simplex_proj_fast(
    float wv, float z, int tid, int lane,
    float* ssort, float* scs, float* swsumf)
{
    float x = wv;

#define SP_SHFL(kk, jj) \
    if (tid < 256) { \
        float o = __shfl_xor_sync(0xffffffffu, x, (jj)); \
        bool keepMax = (((tid & (kk)) == 0) == ((tid & (jj)) == 0)); \
        x = keepMax ? fmaxf(x, o) : fminf(x, o); \
    }
#define SP_SMEM(kk, jj) { \
    if (tid < 256) ssort[tid] = x; \
    __syncthreads(); \
    if (tid < 256) { \
        float o = ssort[tid ^ (jj)]; \
        bool keepMax = (((tid & (kk)) == 0) == ((tid & (jj)) == 0)); \
        x = keepMax ? fmaxf(x, o) : fminf(x, o); \
    } \
    __syncthreads(); }

    SP_SHFL(2, 1)
    SP_SHFL(4, 2)  SP_SHFL(4, 1)
    SP_SHFL(8, 4)  SP_SHFL(8, 2)  SP_SHFL(8, 1)
    SP_SHFL(16, 8) SP_SHFL(16, 4) SP_SHFL(16, 2) SP_SHFL(16, 1)
    SP_SHFL(32, 16) SP_SHFL(32, 8) SP_SHFL(32, 4) SP_SHFL(32, 2) SP_SHFL(32, 1)
    SP_SMEM(64, 32)
    SP_SHFL(64, 16) SP_SHFL(64, 8) SP_SHFL(64, 4) SP_SHFL(64, 2) SP_SHFL(64, 1)
    SP_SMEM(128, 64) SP_SMEM(128, 32)
    SP_SHFL(128, 16) SP_SHFL(128, 8) SP_SHFL(128, 4) SP_SHFL(128, 2) SP_SHFL(128, 1)
    SP_SMEM(256, 128) SP_SMEM(256, 64) SP_SMEM(256, 32)
    SP_SHFL(256, 16) SP_SHFL(256, 8) SP_SHFL(256, 4) SP_SHFL(256, 2) SP_SHFL(256, 1)
#undef SP_SHFL
#undef SP_SMEM

    float inc = 0.0f;
    if (tid < 256) {
        inc = x;
        #pragma unroll
        for (int off = 1; off < 32; off <<= 1) {
            float v = __shfl_up_sync(0xffffffffu, inc, off);
            if (lane >= off) inc += v;
        }
        if (lane == 31) swsumf[tid >> 5] = inc;
    }
    __syncthreads();
    bool cond = false;
    if (tid < 256) {
        float pre = 0.0f;
        int w = tid >> 5;
        #pragma unroll
        for (int q = 0; q < 8; ++q) if (q < w) pre += swsumf[q];
        float cs = inc + pre;
        scs[tid] = cs;
        cond = (x - (cs - z) / (float)(tid + 1)) > 0.0f;
    }
    int rho = __syncthreads_count(cond ? 1 : 0);
    float theta = (scs[rho - 1] - z) / (float)rho;
    return fmaxf(wv - theta, 0.0f);
}

// ---------------------------------------------------------------------------
// u = L^T w from SMEM L (padded, conflict-free columns).
// ---------------------------------------------------------------------------
__device__ __forceinline__ void compute_u_smem(
    int tid, const __half2* sL2, const float* sw, float* sbuf, float* su)
{
    const int q = tid >> 7, cp = tid & 127;
    const __half2* base = sL2 + (size_t)(32 * q) * L_PAD + cp;
    float2 acc = make_float2(0.0f, 0.0f);
    #pragma unroll 8
    for (int m = 0; m < 32; ++m) {
        float2 f = __half22float2(base[m * L_PAD]);
        float wm = sw[32 * q + m];
        acc.x += f.x * wm; acc.y += f.y * wm;
    }
    ((float2*)sbuf)[q * 128 + cp] = acc;
    __syncthreads();
    if (tid < 128) {
        float2 s = make_float2(0.0f, 0.0f);
        #pragma unroll
        for (int r = 0; r < 8; ++r) {
            float2 v = ((const float2*)sbuf)[r * 128 + tid];
            s.x += v.x; s.y += v.y;
        }
        su[2 * tid] = s.x;
        su[2 * tid + 1] = s.y;
    }
}

// ---------------------------------------------------------------------------
// Radix-digest: warp0 scans the 256-bin histogram (descending digits) and
// updates (s_P, s_k) for the K-th largest key.
// ---------------------------------------------------------------------------
__device__ __forceinline__ void radix_digest(
    int lane, int shift, const int* shist, unsigned* s_P, int* s_k)
{
    const unsigned Pc = *s_P;
    const int kcur = *s_k;
    int c[8]; int sum = 0;
    #pragma unroll
    for (int j = 0; j < 8; ++j) { c[j] = shist[255 - (lane * 8 + j)]; sum += c[j]; }
    int incs = sum;
    #pragma unroll
    for (int off = 1; off < 32; off <<= 1) {
        int v = __shfl_up_sync(0xffffffffu, incs, off);
        if (lane >= off) incs += v;
    }
    int run = incs - sum;
    #pragma unroll
    for (int j = 0; j < 8; ++j) {
        int C1 = run; run += c[j];
        if (run >= kcur && C1 < kcur) {
            *s_P = Pc | ((unsigned)(255 - (lane * 8 + j)) << shift);
            *s_k = kcur - C1;
        }
    }
}

// Warp-aggregated histogram add: lanes with equal digit collapse to one
// atomic (leader adds popc). Counts identical to per-lane atomics.
__device__ __forceinline__ void hist_add_agg(int lane, bool doadd, unsigned dg, int* shist)
{
    unsigned key = doadd ? dg : 0xFFFFFFFFu;
    unsigned mm = __match_any_sync(0xffffffffu, key);
    if (doadd) {
        int leader = __ffs(mm) - 1;
        if (lane == leader) atomicAdd(&shist[dg], __popc(mm));
    }
}

// ---------------------------------------------------------------------------
// Persistent solver: cluster of 2 CTAs per batch. Rank r streams the
// n in [128r, 128r+128) half of epsT (default cache policy -> epsT stays
// L2-resident: 65.5MB < 126MB L2); partial losses exchanged via DSMEM.
// ---------------------------------------------------------------------------
extern "C" __global__ void __launch_bounds__(1024, 1) __cluster_dims__(2, 1, 1)
persist_kernel(const float* __restrict__ mu,
               const int* __restrict__ p_crisis, const int* __restrict__ p_lambda,
               float* __restrict__ out)
{
    extern __shared__ char dynraw[];
    __half2* sL2 = (__half2*)dynraw;                    // [256][129] padded L
    float* dynf  = (float*)(dynraw + L_SMEM_BYTES);     // 8000 floats
    float* spart = dynf;                                // [4][2000] loss partials
    int*   ssel  = (int*)dynf;                          // [2000] selected idx (alias)
    float* sbuf  = dynf + 2048;                         // [2048]
    float2* svv2 = (float2*)(dynf + 4352);              // [128]  v pairs

    __shared__ float su[256], sw[256], ssort[256], scs[256];
    __shared__ unsigned skey[NS];
    __shared__ int shist[256];
    __shared__ float swsumf[8];
    __shared__ int swsum[32];
    __shared__ unsigned s_P;
    __shared__ int s_k;

    const int b = blockIdx.x >> 1;
    const unsigned int rank = blockIdx.x & 1;
    const unsigned int prank = rank ^ 1;
    const int tid = threadIdx.x;
    const int lane = tid & 31;
    const int warp = tid >> 5;

    const float crisis = (float)(*p_crisis);
    const int lam = *p_lambda;
    const float lamscale = (lam > 0) ? (1.0f + 1.0f / fmaxf((float)lam, 0.1f)) : 1.0f;
    const float z = 1.0f - 0.5f * crisis;
    const float flme = (tid == BIL) ? 0.5f * crisis : 0.0f;
    float mue = 0.0f;
    if (tid < 256) mue = mu[b * NN + tid] * lamscale;

    // load L into padded smem (bank-conflict-free in both orientations)
    {
        const __half2* Lg2 = (const __half2*)(g_L16 + (size_t)b * NN * NN);
        for (int idx = tid; idx < NN * 128; idx += 1024) {
            int row = idx >> 7, col = idx & 127;
            sL2[row * L_PAD + col] = Lg2[idx];
        }
    }

    // loss-phase mapping: 1000 active threads; nc in [0,4) owns 32 n's within
    // this rank's 128-n half, sg in [0,250) owns 8 scenarios.
    const int nc = tid / 250;
    const int sg = tid - nc * 250;
    const bool lactive = (tid < 1000);
    const unsigned int spart_a = smem_u32(spart);

    // ---- init: w0 = proj(uniform), u = L^T w0
    {
        float v = (1.0f / (float)NN) - flme;
        float pw = simplex_proj_fast(v, z, tid, lane, ssort, scs, swsumf) + flme;
        if (tid < 256) sw[tid] = pw;
        __syncthreads();
        compute_u_smem(tid, sL2, sw, sbuf, su);
        __syncthreads();
    }
    cluster_sync_();   // both ranks ready before first loss exchange cycle

    for (int t = 0; t < NITERS; ++t) {
        // ---- loss phase: partial dots over this rank's 128 n's
        // default-policy loads keep epsT L2-resident across iterations
        if (lactive) {
            const int nbase = (int)rank * 128 + nc * 32;
            const __half* base = g_epsT + ((size_t)(b * NN + nbase)) * NS + 8 * sg;
            float a0=0.f,a1=0.f,a2=0.f,a3=0.f,a4=0.f,a5=0.f,a6=0.f,a7=0.f;
            #pragma unroll 8
            for (int n = 0; n < 32; ++n) {
                uint4 raw = __ldg((const uint4*)(base + (size_t)n * NS));
                float un = su[nbase + n];
                float2 f0 = __half22float2(*(const __half2*)&raw.x);
                float2 f1 = __half22float2(*(const __half2*)&raw.y);
                float2 f2 = __half22float2(*(const __half2*)&raw.z);
                float2 f3 = __half22float2(*(const __half2*)&raw.w);
                a0 += f0.x * un; a1 += f0.y * un;
                a2 += f1.x * un; a3 += f1.y * un;
                a4 += f2.x * un; a5 += f2.y * un;
                a6 += f3.x * un; a7 += f3.y * un;
            }
            float* o = spart + nc * NS + 8 * sg;
            o[0]=a0; o[1]=a1; o[2]=a2; o[3]=a3; o[4]=a4; o[5]=a5; o[6]=a6; o[7]=a7;
        }
        // zero pass-0 histogram + select state while loss stores drain
        if (tid < 256) shist[tid] = 0;
        if (tid == 0) { s_P = 0u; s_k = KK; }
        __syncthreads();

        // combine my 4 sub-partials in place: spart[s] = my half-dot
        for (int s = tid; s < NS; s += 1024)
            spart[s] = (spart[s] + spart[NS + s]) + (spart[2 * NS + s] + spart[3 * NS + s]);
        __syncthreads();
        cluster_sync_();   // my half-dots visible to peer

        // full losses via DSMEM read of peer's half -> sortable keys
        // + FUSED radix pass-0 histogram (warp-aggregated)
        for (int base0 = 0; base0 < NS; base0 += 1024) {
            int s = base0 + tid;
            bool valid = s < NS;
            unsigned key = 0u;
            if (valid) {
                float pv = ld_peer_f32(spart_a + 4 * (unsigned int)s, prank);
                float loss = -(spart[s] + pv);
                unsigned ub = __float_as_uint(loss);
                key = (ub & 0x80000000u) ? ~ub : (ub | 0x80000000u);
                skey[s] = key;
            }
            hist_add_agg(lane, valid, key >> 24, shist);
        }
        __syncthreads();
        if (warp == 0) radix_digest(lane, 24, shist, &s_P, &s_k);
        __syncthreads();
        cluster_sync_();   // peer done reading my spart; aliases may go live

        // ---- radix passes 1..3 (full key sweep, warp-aggregated histogram)
        #pragma unroll
        for (int p = 1; p < 4; ++p) {
            const int shift = 24 - 8 * p;
            if (tid < 256) shist[tid] = 0;
            __syncthreads();
            const unsigned Pc = s_P;
            for (int base0 = 0; base0 < NS; base0 += 1024) {
                int s = base0 + tid;
                bool valid = s < NS;
                unsigned key = valid ? skey[s] : 0u;
                bool match = valid && ((key >> (shift + 8)) == (Pc >> (shift + 8)));
                hist_add_agg(lane, match, (key >> shift) & 255u, shist);
            }
            __syncthreads();
            if (warp == 0) radix_digest(lane, shift, shist, &s_P, &s_k);
            __syncthreads();
        }
        const unsigned T = s_P;

        // ---- deterministic compaction of selected scenarios
        bool m0 = skey[tid] >= T;
        bool m1 = (tid + 1024 < NS) && (skey[tid + 1024] >= T);
        int cnt = (int)m0 + (int)m1;
        {
            int incs = cnt;
            #pragma unroll
            for (int off = 1; off < 32; off <<= 1) {
                int v = __shfl_up_sync(0xffffffffu, incs, off);
                if (lane >= off) incs += v;
            }
            if (lane == 31) swsum[warp] = incs;
            __syncthreads();
            if (warp == 0) {
                int v = swsum[lane];
                #pragma unroll
                for (int off = 1; off < 32; off <<= 1) {
                    int x = __shfl_up_sync(0xffffffffu, v, off);
                    if (lane >= off) v += x;
                }
                swsum[lane] = v;
            }
            __syncthreads();
            int ofs = (incs - cnt) + (warp > 0 ? swsum[warp - 1] : 0);
            if (m0) ssel[ofs++] = tid;
            if (m1) ssel[ofs] = tid + 1024;
        }
        __syncthreads();
        const int total = swsum[31];
        const float coef = 1.0f / fmaxf((float)total, (float)KK);
        const float summ = (float)total * coef;

        // ---- v = coef * sum_{selected s} eps16[b,s,:]  (8-way row split,
        // 4-way unrolled for MLP; evict-first so the random gather never
        // pollutes epsT's L2 residency)
        {
            const int grp = tid >> 7, cp = tid & 127;
            const __half2* e2 = (const __half2*)g_eps16 + (size_t)b * NS * 128;
            float2 acc = make_float2(0.0f, 0.0f);
            int i = grp;
            for (; i + 24 < total; i += 32) {
                float2 fa = __half22float2(__ldcs(e2 + (size_t)ssel[i]      * 128 + cp));
                float2 fb = __half22float2(__ldcs(e2 + (size_t)ssel[i + 8]  * 128 + cp));
                float2 fc = __half22float2(__ldcs(e2 + (size_t)ssel[i + 16] * 128 + cp));
                float2 fd = __half22float2(__ldcs(e2 + (size_t)ssel[i + 24] * 128 + cp));
                acc.x += (fa.x + fb.x) + (fc.x + fd.x);
                acc.y += (fa.y + fb.y) + (fc.y + fd.y);
            }
            for (; i < total; i += 8) {
                float2 fa = __half22float2(__ldcs(e2 + (size_t)ssel[i] * 128 + cp));
                acc.x += fa.x; acc.y += fa.y;
            }
            ((float2*)sbuf)[grp * 128 + cp] = acc;
        }
        __syncthreads();
        if (tid < 128) {
            float2 s = make_float2(0.0f, 0.0f);
            #pragma unroll
            for (int r = 0; r < 8; ++r) {
                float2 v = ((const float2*)sbuf)[r * 128 + tid];
                s.x += v.x; s.y += v.y;
            }
            svv2[tid] = make_float2(s.x * coef, s.y * coef);
        }
        __syncthreads();

        // ---- lv[n] = sum_m L[n][m] v[m] from SMEM L (row access, conflict-free)
        {
            const int q = tid >> 8, n = tid & 255;
            const __half2* rowp = sL2 + (size_t)n * L_PAD + 32 * q;
            float acc = 0.0f;
            #pragma unroll 8
            for (int mp = 0; mp < 32; ++mp) {
                float2 f = __half22float2(rowp[mp]);
                float2 vv = svv2[32 * q + mp];
                acc += f.x * vv.x + f.y * vv.y;
            }
            sbuf[q * 256 + n] = acc;   // no alias with svv2; barrier not needed
        }
        __syncthreads();

        // ---- projected update (threads < 256 own components)
        const float lr = 0.5f / sqrtf((float)t + 1.0f);
        float wv = 0.0f;
        if (tid < 256) {
            float lv = sbuf[tid] + sbuf[256 + tid] + sbuf[512 + tid] + sbuf[768 + tid];
            const float gval = -(summ * mue + lv);
            wv = sw[tid] - lr * gval - flme;
        }
        __syncthreads();
        float pw = simplex_proj_fast(wv, z, tid, lane, ssort, scs, swsumf) + flme;
        if (tid < 256) sw[tid] = pw;
        __syncthreads();

        if (t == NITERS - 1) {
            // ---- final clamp + renormalize (rank 0 writes)
            float wc = (tid < 256) ? fmaxf(pw, 0.0f) : 0.0f;
            float r = wc;
            if (tid < 256) {
                #pragma unroll
                for (int off = 16; off > 0; off >>= 1)
                    r += __shfl_down_sync(0xffffffffu, r, off);
                if (lane == 0) swsumf[tid >> 5] = r;
            }
            __syncthreads();
            if (rank == 0 && tid < 256) {
                float s = 0.0f;
                #pragma unroll
                for (int q = 0; q < 8; ++q) s += swsumf[q];
                out[b * NN + tid] = wc / (s + 1e-8f);
            }
        } else {
            compute_u_smem(tid, sL2, sw, sbuf, su);
            __syncthreads();   // su stable & dyn free before next loss phase
        }
    }
    cluster_sync_();   // no rank exits while peer may still DSMEM-read
}

// ---------------------------------------------------------------------------
extern "C" void kernel_launch(void* const* d_in, const int* in_sizes, int n_in,
                              void* d_out, int out_size)
{
    const float* mu     = (const float*)d_in[0];
    const float* sigma  = (const float*)d_in[1];
    const float* eps    = (const float*)d_in[2];
    const int*   crisis = (const int*)d_in[3];
    const int*   lambda = (const int*)d_in[4];
    float* out = (float*)d_out;

    cudaFuncSetAttribute(chol_kernel, cudaFuncAttributeMaxDynamicSharedMemorySize,
                         32896 * sizeof(float));
    cudaFuncSetAttribute(persist_kernel, cudaFuncAttributeMaxDynamicSharedMemorySize,
                         DYN_BYTES);

    conv_kernel<<<16000, 256>>>(eps);
    transpose_kernel<<<NB * 256, 256>>>(eps);
    chol_kernel<<<NB, 256, 32896 * sizeof(float)>>>(sigma);
    persist_kernel<<<NB * 2, 1024, DYN_BYTES>>>(mu, crisis, lambda, out);
}

// round 16
// speedup vs baseline: 1.0998x; 1.0458x over previous
#include <cuda_runtime.h>
#include <cuda_fp16.h>
#include <cstdint>
#include <math.h>

// Problem constants
#define NB 64
#define NN 256
#define NS 2000
#define KK 100
#define BIL 4
#define NITERS 200

#define L_PAD 129                       // half2 per padded row (128 + 1)
#define L_SMEM_BYTES (NN * L_PAD * 4)   // 132096 B
#define DYN_FLOATS 8000
#define DYN_BYTES (L_SMEM_BYTES + DYN_FLOATS * 4)   // 164096 B

// Device scratch
__device__ __align__(16) __half g_L16[(size_t)NB * NN * NN];   // 8.4MB  L[b][m][n]
__device__ __align__(16) __half g_eps16[(size_t)NB * NS * NN]; // 65.5MB row-major [b][s][n]
__device__ __align__(16) __half g_epsT[(size_t)NB * NN * NS];  // 65.5MB transposed [b][n][s]

// ---------------------------------------------------------------------------
__device__ __forceinline__ unsigned int smem_u32(const void* p) {
    unsigned int a;
    asm("{ .reg .u64 t; cvta.to.shared.u64 t, %1; cvt.u32.u64 %0, t; }"
        : "=r"(a) : "l"(p));
    return a;
}
__device__ __forceinline__ float ld_peer_f32(unsigned int addr, unsigned int prank) {
    unsigned int pa;
    asm("mapa.shared::cluster.u32 %0, %1, %2;" : "=r"(pa) : "r"(addr), "r"(prank));
    float v;
    asm volatile("ld.shared::cluster.f32 %0, [%1];" : "=f"(v) : "r"(pa));
    return v;
}
__device__ __forceinline__ void cluster_sync_() {
    asm volatile("barrier.cluster.arrive.aligned;" ::: "memory");
    asm volatile("barrier.cluster.wait.aligned;" ::: "memory");
}

// ---------------------------------------------------------------------------
// eps fp32 -> fp16 row-major (one thread per 8 elements)
// ---------------------------------------------------------------------------
extern "C" __global__ void __launch_bounds__(256)
conv_kernel(const float* __restrict__ eps)
{
    size_t gid = (size_t)blockIdx.x * blockDim.x + threadIdx.x;
    const size_t total8 = (size_t)NB * NS * NN / 8;
    if (gid >= total8) return;
    const float4* e4 = (const float4*)eps;
    float4 f0 = __ldcs(e4 + 2 * gid);
    float4 f1 = __ldcs(e4 + 2 * gid + 1);
    uint4 o;
    *(__half2*)&o.x = __floats2half2_rn(f0.x, f0.y);
    *(__half2*)&o.y = __floats2half2_rn(f0.z, f0.w);
    *(__half2*)&o.z = __floats2half2_rn(f1.x, f1.y);
    *(__half2*)&o.w = __floats2half2_rn(f1.z, f1.w);
    ((uint4*)g_eps16)[gid] = o;
}

// ---------------------------------------------------------------------------
// eps fp32 -> fp16 transposed [b][n][s], tiled 64(s) x 32(n)
// ---------------------------------------------------------------------------
extern "C" __global__ void __launch_bounds__(256)
transpose_kernel(const float* __restrict__ eps)
{
    __shared__ float tile[64][33];
    const int blk = blockIdx.x;
    const int b = blk >> 8;
    const int rest = blk & 255;
    const int st = rest >> 3;
    const int nt = rest & 7;
    const int s0 = st * 64, n0 = nt * 32;
    const int tid = threadIdx.x;

    #pragma unroll
    for (int k = 0; k < 8; ++k) {
        int idx = tid + 256 * k;
        int s = idx >> 5, n = idx & 31;
        float v = 0.0f;
        if (s0 + s < NS) v = __ldcs(&eps[((size_t)b * NS + s0 + s) * NN + n0 + n]);
        tile[s][n] = v;
    }
    __syncthreads();
    #pragma unroll
    for (int k = 0; k < 4; ++k) {
        int idx = tid + 256 * k;
        int n = idx >> 5, sp = idx & 31;
        int s = 2 * sp;
        if (s0 + s < NS) {
            __half2 h = __floats2half2_rn(tile[s][n], tile[s + 1][n]);
            *(__half2*)(g_epsT + ((size_t)b * NN + n0 + n) * NS + s0 + s) = h;
        }
    }
}

// ---------------------------------------------------------------------------
// Cholesky: one block per batch, packed lower triangle in smem; fp16 L out.
// ---------------------------------------------------------------------------
__device__ __forceinline__ int tri_row_of(int idx) {
    float f = sqrtf(8.0f * (float)idx + 1.0f);
    int i = (int)((f - 1.0f) * 0.5f);
    while ((i + 1) * (i + 2) / 2 <= idx) ++i;
    while (i * (i + 1) / 2 > idx) --i;
    return i;
}

extern "C" __global__ void __launch_bounds__(256)
chol_kernel(const float* __restrict__ sigma) {
    extern __shared__ float sm[];   // 32896 floats
    const int b = blockIdx.x;
    const int tid = threadIdx.x;
    const float* A = sigma + (size_t)b * NN * NN;

    for (int idx = tid; idx < 32896; idx += 256) {
        int i = tri_row_of(idx);
        int j = idx - i * (i + 1) / 2;
        float v = A[i * NN + j];
        if (i == j) v += 1e-4f;
        sm[idx] = v;
    }
    __syncthreads();

    __shared__ float sdiag;
    float acc = 0.0f;
    const int base_i = tid * (tid + 1) / 2;

    for (int j = 0; j < NN; ++j) {
        if (tid == j) {
            float d = sm[j * (j + 1) / 2 + j] - acc;
            sdiag = sqrtf(fmaxf(d, 1e-20f));
            sm[j * (j + 1) / 2 + j] = sdiag;
        }
        __syncthreads();
        float dinv = 1.0f / sdiag;
        if (tid > j) {
            const int base_j = j * (j + 1) / 2;
            float s = sm[base_i + j];
            int k = 0;
            for (; k + 4 <= j; k += 4) {
                s -= sm[base_i + k]     * sm[base_j + k];
                s -= sm[base_i + k + 1] * sm[base_j + k + 1];
                s -= sm[base_i + k + 2] * sm[base_j + k + 2];
                s -= sm[base_i + k + 3] * sm[base_j + k + 3];
            }
            for (; k < j; ++k) s -= sm[base_i + k] * sm[base_j + k];
            float lij = s * dinv;
            sm[base_i + j] = lij;
            acc += lij * lij;
        }
        __syncthreads();
    }

    __half* Lb = g_L16 + (size_t)b * NN * NN;
    for (int idx = tid; idx < NN * NN; idx += 256) {
        int i = idx >> 8, j = idx & 255;
        Lb[idx] = __float2half_rn((j <= i) ? sm[i * (i + 1) / 2 + j] : 0.0f);
    }
}

// ---------------------------------------------------------------------------
// Fast simplex projection (values on tid<256).
// ---------------------------------------------------------------------------
__device__ __forceinline__ float simplex_proj_fast(
    float wv, float z, int tid, int lane,
    float* ssort, float* scs, float* swsumf)
{
    float x = wv;

#define SP_SHFL(kk, jj) \
    if (tid < 256) { \
        float o = __shfl_xor_sync(0xffffffffu, x, (jj)); \
        bool keepMax = (((tid & (kk)) == 0) == ((tid & (jj)) == 0)); \
        x = keepMax ? fmaxf(x, o) : fminf(x, o); \
    }
#define SP_SMEM(kk, jj) { \
    if (tid < 256) ssort[tid] = x; \
    __syncthreads(); \
    if (tid < 256) { \
        float o = ssort[tid ^ (jj)]; \
        bool keepMax = (((tid & (kk)) == 0) == ((tid & (jj)) == 0)); \
        x = keepMax ? fmaxf(x, o) : fminf(x, o); \
    } \
    __syncthreads(); }

    SP_SHFL(2, 1)
    SP_SHFL(4, 2)  SP_SHFL(4, 1)
    SP_SHFL(8, 4)  SP_SHFL(8, 2)  SP_SHFL(8, 1)
    SP_SHFL(16, 8) SP_SHFL(16, 4) SP_SHFL(16, 2) SP_SHFL(16, 1)
    SP_SHFL(32, 16) SP_SHFL(32, 8) SP_SHFL(32, 4) SP_SHFL(32, 2) SP_SHFL(32, 1)
    SP_SMEM(64, 32)
    SP_SHFL(64, 16) SP_SHFL(64, 8) SP_SHFL(64, 4) SP_SHFL(64, 2) SP_SHFL(64, 1)
    SP_SMEM(128, 64) SP_SMEM(128, 32)
    SP_SHFL(128, 16) SP_SHFL(128, 8) SP_SHFL(128, 4) SP_SHFL(128, 2) SP_SHFL(128, 1)
    SP_SMEM(256, 128) SP_SMEM(256, 64) SP_SMEM(256, 32)
    SP_SHFL(256, 16) SP_SHFL(256, 8) SP_SHFL(256, 4) SP_SHFL(256, 2) SP_SHFL(256, 1)
#undef SP_SHFL
#undef SP_SMEM

    float inc = 0.0f;
    if (tid < 256) {
        inc = x;
        #pragma unroll
        for (int off = 1; off < 32; off <<= 1) {
            float v = __shfl_up_sync(0xffffffffu, inc, off);
            if (lane >= off) inc += v;
        }
        if (lane == 31) swsumf[tid >> 5] = inc;
    }
    __syncthreads();
    bool cond = false;
    if (tid < 256) {
        float pre = 0.0f;
        int w = tid >> 5;
        #pragma unroll
        for (int q = 0; q < 8; ++q) if (q < w) pre += swsumf[q];
        float cs = inc + pre;
        scs[tid] = cs;
        cond = (x - (cs - z) / (float)(tid + 1)) > 0.0f;
    }
    int rho = __syncthreads_count(cond ? 1 : 0);
    float theta = (scs[rho - 1] - z) / (float)rho;
    return fmaxf(wv - theta, 0.0f);
}

// ---------------------------------------------------------------------------
// u = L^T w from SMEM L (padded, conflict-free columns).
// ---------------------------------------------------------------------------
__device__ __forceinline__ void compute_u_smem(
    int tid, const __half2* sL2, const float* sw, float* sbuf, float* su)
{
    const int q = tid >> 7, cp = tid & 127;
    const __half2* base = sL2 + (size_t)(32 * q) * L_PAD + cp;
    float2 acc = make_float2(0.0f, 0.0f);
    #pragma unroll 8
    for (int m = 0; m < 32; ++m) {
        float2 f = __half22float2(base[m * L_PAD]);
        float wm = sw[32 * q + m];
        acc.x += f.x * wm; acc.y += f.y * wm;
    }
    ((float2*)sbuf)[q * 128 + cp] = acc;
    __syncthreads();
    if (tid < 128) {
        float2 s = make_float2(0.0f, 0.0f);
        #pragma unroll
        for (int r = 0; r < 8; ++r) {
            float2 v = ((const float2*)sbuf)[r * 128 + tid];
            s.x += v.x; s.y += v.y;
        }
        su[2 * tid] = s.x;
        su[2 * tid + 1] = s.y;
    }
}

// ---------------------------------------------------------------------------
// Wide radix digest: 256 threads scan an nbins-bin histogram in DESCENDING
// digit order and update (s_P, s_k) to locate the K-th largest key's digit.
// nbins = 2048 or 1024; per-thread chunk = nbins/256 descending positions.
// Unique writer (exactly one crossing); others only read at entry.
// ---------------------------------------------------------------------------
__device__ __forceinline__ void radix_digest_wide(
    int tid, int lane, int shift, int nbins,
    const int* shist, int* swsum, unsigned* s_P, int* s_k)
{
    const unsigned Pc = *s_P;
    const int kcur = *s_k;
    const int per = nbins >> 8;   // 8 (2048) or 4 (1024)
    int cbin[8];
    int mysum = 0;
    if (tid < 256) {
        #pragma unroll
        for (int j = 0; j < 8; ++j) {
            if (j < per) {
                int bin = nbins - 1 - (tid * per + j);   // descending
                cbin[j] = shist[bin];
                mysum += cbin[j];
            }
        }
        // inclusive warp scan of mysum
        int incs = mysum;
        #pragma unroll
        for (int off = 1; off < 32; off <<= 1) {
            int v = __shfl_up_sync(0xffffffffu, incs, off);
            if (lane >= off) incs += v;
        }
        if (lane == 31) swsum[tid >> 5] = incs;   // 8 warp totals
        // cross-warp exclusive prefix after barrier below
        __syncthreads();
        int pre = 0;
        int w = tid >> 5;
        #pragma unroll
        for (int q = 0; q < 8; ++q) if (q < w) pre += swsum[q];
        int run = pre + incs - mysum;   // exclusive prefix of my chunk
        #pragma unroll
        for (int j = 0; j < 8; ++j) {
            if (j < per) {
                int C1 = run; run += cbin[j];
                if (run >= kcur && C1 < kcur) {
                    *s_P = Pc | ((unsigned)(nbins - 1 - (tid * per + j)) << shift);
                    *s_k = kcur - C1;
                }
            }
        }
    } else {
        __syncthreads();   // match the barrier inside the tid<256 path
    }
}

// ---------------------------------------------------------------------------
// Persistent solver: cluster of 2 CTAs per batch. Rank r streams the
// n in [128r, 128r+128) half of epsT (default cache policy -> epsT stays
// L2-resident: 65.5MB < 126MB L2); partial losses exchanged via DSMEM.
// Select: 3-pass radix (11/11/10-bit digits), pass 0 fused into key build.
// ---------------------------------------------------------------------------
extern "C" __global__ void __launch_bounds__(1024, 1) __cluster_dims__(2, 1, 1)
persist_kernel(const float* __restrict__ mu,
               const int* __restrict__ p_crisis, const int* __restrict__ p_lambda,
               float* __restrict__ out)
{
    extern __shared__ char dynraw[];
    __half2* sL2 = (__half2*)dynraw;                    // [256][129] padded L
    float* dynf  = (float*)(dynraw + L_SMEM_BYTES);     // 8000 floats
    float* spart = dynf;                                // [4][2000] loss partials
    int*   ssel  = (int*)dynf;                          // [2000] (alias)
    float* sbuf  = dynf + 2048;                         // [2048]
    float2* svv2 = (float2*)(dynf + 4352);              // [128]  v pairs

    __shared__ float su[256], sw[256], ssort[256], scs[256];
    __shared__ unsigned skey[NS];
    __shared__ int shist[2048];
    __shared__ float swsumf[8];
    __shared__ int swsum[32];
    __shared__ unsigned s_P;
    __shared__ int s_k;

    const int b = blockIdx.x >> 1;
    const unsigned int rank = blockIdx.x & 1;
    const unsigned int prank = rank ^ 1;
    const int tid = threadIdx.x;
    const int lane = tid & 31;
    const int warp = tid >> 5;

    const float crisis = (float)(*p_crisis);
    const int lam = *p_lambda;
    const float lamscale = (lam > 0) ? (1.0f + 1.0f / fmaxf((float)lam, 0.1f)) : 1.0f;
    const float z = 1.0f - 0.5f * crisis;
    const float flme = (tid == BIL) ? 0.5f * crisis : 0.0f;
    float mue = 0.0f;
    if (tid < 256) mue = mu[b * NN + tid] * lamscale;

    // load L into padded smem (bank-conflict-free in both orientations)
    {
        const __half2* Lg2 = (const __half2*)(g_L16 + (size_t)b * NN * NN);
        for (int idx = tid; idx < NN * 128; idx += 1024) {
            int row = idx >> 7, col = idx & 127;
            sL2[row * L_PAD + col] = Lg2[idx];
        }
    }

    // loss-phase mapping: 1000 active threads; nc in [0,4) owns 32 n's within
    // this rank's 128-n half, sg in [0,250) owns 8 scenarios.
    const int nc = tid / 250;
    const int sg = tid - nc * 250;
    const bool lactive = (tid < 1000);
    const unsigned int spart_a = smem_u32(spart);

    // ---- init: w0 = proj(uniform), u = L^T w0
    {
        float v = (1.0f / (float)NN) - flme;
        float pw = simplex_proj_fast(v, z, tid, lane, ssort, scs, swsumf) + flme;
        if (tid < 256) sw[tid] = pw;
        __syncthreads();
        compute_u_smem(tid, sL2, sw, sbuf, su);
        __syncthreads();
    }
    cluster_sync_();   // both ranks ready before first loss exchange cycle

    for (int t = 0; t < NITERS; ++t) {
        // ---- loss phase: partial dots over this rank's 128 n's
        // default-policy loads keep epsT L2-resident across iterations
        if (lactive) {
            const int nbase = (int)rank * 128 + nc * 32;
            const __half* base = g_epsT + ((size_t)(b * NN + nbase)) * NS + 8 * sg;
            float a0=0.f,a1=0.f,a2=0.f,a3=0.f,a4=0.f,a5=0.f,a6=0.f,a7=0.f;
            #pragma unroll 8
            for (int n = 0; n < 32; ++n) {
                uint4 raw = __ldg((const uint4*)(base + (size_t)n * NS));
                float un = su[nbase + n];
                float2 f0 = __half22float2(*(const __half2*)&raw.x);
                float2 f1 = __half22float2(*(const __half2*)&raw.y);
                float2 f2 = __half22float2(*(const __half2*)&raw.z);
                float2 f3 = __half22float2(*(const __half2*)&raw.w);
                a0 += f0.x * un; a1 += f0.y * un;
                a2 += f1.x * un; a3 += f1.y * un;
                a4 += f2.x * un; a5 += f2.y * un;
                a6 += f3.x * un; a7 += f3.y * un;
            }
            float* o = spart + nc * NS + 8 * sg;
            o[0]=a0; o[1]=a1; o[2]=a2; o[3]=a3; o[4]=a4; o[5]=a5; o[6]=a6; o[7]=a7;
        }
        // zero pass-0 histogram (2048 bins) + select state while stores drain
        shist[tid] = 0; shist[tid + 1024] = 0;
        if (tid == 0) { s_P = 0u; s_k = KK; }
        __syncthreads();

        // combine my 4 sub-partials in place: spart[s] = my half-dot
        for (int s = tid; s < NS; s += 1024)
            spart[s] = (spart[s] + spart[NS + s]) + (spart[2 * NS + s] + spart[3 * NS + s]);
        __syncthreads();
        cluster_sync_();   // my half-dots visible to peer

        // full losses via DSMEM read of peer's half -> monotone sortable keys
        // + FUSED radix pass-0 histogram (top 11 bits)
        for (int s = tid; s < NS; s += 1024) {
            float pv = ld_peer_f32(spart_a + 4 * (unsigned int)s, prank);
            float loss = -(spart[s] + pv);
            unsigned ub = __float_as_uint(loss);
            unsigned key = (ub & 0x80000000u) ? ~ub : (ub | 0x80000000u);
            skey[s] = key;
            atomicAdd(&shist[key >> 21], 1);
        }
        __syncthreads();
        radix_digest_wide(tid, lane, 21, 2048, shist, swsum, &s_P, &s_k);
        __syncthreads();
        cluster_sync_();   // peer done reading my spart; aliases may go live

        // ---- radix pass 1: middle 11 bits among keys matching pass-0 digit
        {
            shist[tid] = 0; shist[tid + 1024] = 0;
            __syncthreads();
            const unsigned Pc = s_P;
            for (int s = tid; s < NS; s += 1024) {
                unsigned key = skey[s];
                if ((key >> 21) == (Pc >> 21))
                    atomicAdd(&shist[(key >> 10) & 2047u], 1);
            }
            __syncthreads();
            radix_digest_wide(tid, lane, 10, 2048, shist, swsum, &s_P, &s_k);
            __syncthreads();
        }
        // ---- radix pass 2: low 10 bits among keys matching passes 0-1
        {
            shist[tid] = 0;   // only 1024 bins needed
            __syncthreads();
            const unsigned Pc = s_P;
            for (int s = tid; s < NS; s += 1024) {
                unsigned key = skey[s];
                if ((key >> 10) == (Pc >> 10))
                    atomicAdd(&shist[key & 1023u], 1);
            }
            __syncthreads();
            radix_digest_wide(tid, lane, 0, 1024, shist, swsum, &s_P, &s_k);
            __syncthreads();
        }
        const unsigned T = s_P;

        // ---- deterministic compaction of selected scenarios
        bool m0 = skey[tid] >= T;
        bool m1 = (tid + 1024 < NS) && (skey[tid + 1024] >= T);
        int cnt = (int)m0 + (int)m1;
        {
            int incs = cnt;
            #pragma unroll
            for (int off = 1; off < 32; off <<= 1) {
                int v = __shfl_up_sync(0xffffffffu, incs, off);
                if (lane >= off) incs += v;
            }
            if (lane == 31) swsum[warp] = incs;
            __syncthreads();
            if (warp == 0) {
                int v = swsum[lane];
                #pragma unroll
                for (int off = 1; off < 32; off <<= 1) {
                    int x = __shfl_up_sync(0xffffffffu, v, off);
                    if (lane >= off) v += x;
                }
                swsum[lane] = v;
            }
            __syncthreads();
            int ofs = (incs - cnt) + (warp > 0 ? swsum[warp - 1] : 0);
            if (m0) ssel[ofs++] = tid;
            if (m1) ssel[ofs] = tid + 1024;
        }
        __syncthreads();
        const int total = swsum[31];
        const float coef = 1.0f / fmaxf((float)total, (float)KK);
        const float summ = (float)total * coef;

        // ---- v = coef * sum_{selected s} eps16[b,s,:]  (8-way row split,
        // 2-way unrolled; evict-first so the random gather never pollutes
        // epsT's L2 residency)
        {
            const int grp = tid >> 7, cp = tid & 127;
            const __half2* e2 = (const __half2*)g_eps16 + (size_t)b * NS * 128;
            float2 acc = make_float2(0.0f, 0.0f);
            int i = grp;
            for (; i + 8 < total; i += 16) {
                float2 fa = __half22float2(__ldcs(e2 + (size_t)ssel[i] * 128 + cp));
                float2 fb = __half22float2(__ldcs(e2 + (size_t)ssel[i + 8] * 128 + cp));
                acc.x += fa.x + fb.x; acc.y += fa.y + fb.y;
            }
            if (i < total) {
                float2 fa = __half22float2(__ldcs(e2 + (size_t)ssel[i] * 128 + cp));
                acc.x += fa.x; acc.y += fa.y;
            }
            ((float2*)sbuf)[grp * 128 + cp] = acc;
        }
        __syncthreads();
        if (tid < 128) {
            float2 s = make_float2(0.0f, 0.0f);
            #pragma unroll
            for (int r = 0; r < 8; ++r) {
                float2 v = ((const float2*)sbuf)[r * 128 + tid];
                s.x += v.x; s.y += v.y;
            }
            svv2[tid] = make_float2(s.x * coef, s.y * coef);
        }
        __syncthreads();

        // ---- lv[n] = sum_m L[n][m] v[m] from SMEM L (row access, conflict-free)
        {
            const int q = tid >> 8, n = tid & 255;
            const __half2* rowp = sL2 + (size_t)n * L_PAD + 32 * q;
            float acc = 0.0f;
            #pragma unroll 8
            for (int mp = 0; mp < 32; ++mp) {
                float2 f = __half22float2(rowp[mp]);
                float2 vv = svv2[32 * q + mp];
                acc += f.x * vv.x + f.y * vv.y;
            }
            __syncthreads();   // svv2 reads done before sbuf overwrite
            sbuf[q * 256 + n] = acc;
        }
        __syncthreads();

        // ---- projected update (threads < 256 own components)
        const float lr = 0.5f / sqrtf((float)t + 1.0f);
        float wv = 0.0f;
        if (tid < 256) {
            float lv = sbuf[tid] + sbuf[256 + tid] + sbuf[512 + tid] + sbuf[768 + tid];
            const float gval = -(summ * mue + lv);
            wv = sw[tid] - lr * gval - flme;
        }
        __syncthreads();
        float pw = simplex_proj_fast(wv, z, tid, lane, ssort, scs, swsumf) + flme;
        if (tid < 256) sw[tid] = pw;
        __syncthreads();

        if (t == NITERS - 1) {
            // ---- final clamp + renormalize (rank 0 writes)
            float wc = (tid < 256) ? fmaxf(pw, 0.0f) : 0.0f;
            float r = wc;
            if (tid < 256) {
                #pragma unroll
                for (int off = 16; off > 0; off >>= 1)
                    r += __shfl_down_sync(0xffffffffu, r, off);
                if (lane == 0) swsumf[tid >> 5] = r;
            }
            __syncthreads();
            if (rank == 0 && tid < 256) {
                float s = 0.0f;
                #pragma unroll
                for (int q = 0; q < 8; ++q) s += swsumf[q];
                out[b * NN + tid] = wc / (s + 1e-8f);
            }
        } else {
            compute_u_smem(tid, sL2, sw, sbuf, su);
            __syncthreads();   // su stable & dyn free before next loss phase
        }
    }
    cluster_sync_();   // no rank exits while peer may still DSMEM-read
}

// ---------------------------------------------------------------------------
extern "C" void kernel_launch(void* const* d_in, const int* in_sizes, int n_in,
                              void* d_out, int out_size)
{
    const float* mu     = (const float*)d_in[0];
    const float* sigma  = (const float*)d_in[1];
    const float* eps    = (const float*)d_in[2];
    const int*   crisis = (const int*)d_in[3];
    const int*   lambda = (const int*)d_in[4];
    float* out = (float*)d_out;

    cudaFuncSetAttribute(chol_kernel, cudaFuncAttributeMaxDynamicSharedMemorySize,
                         32896 * sizeof(float));
    cudaFuncSetAttribute(persist_kernel, cudaFuncAttributeMaxDynamicSharedMemorySize,
                         DYN_BYTES);

    conv_kernel<<<16000, 256>>>(eps);
    transpose_kernel<<<NB * 256, 256>>>(eps);
    chol_kernel<<<NB, 256, 32896 * sizeof(float)>>>(sigma);
    persist_kernel<<<NB * 2, 1024, DYN_BYTES>>>(mu, crisis, lambda, out);
}